// round 15
// baseline (speedup 1.0000x reference)
#include <cuda_runtime.h>
#include <cstdint>

// SignalDualBackground: out[b,c,s,t] = (1 - spikes[b,c,s,t]) * stat[b,c,t]
//   x[b,c,t]  = mean_s spikes[b,c,s,t]            (S=64)
//   stat[.,t] = beta*stat[.,t-1] + (1-beta)*x[.,t], stat[.,-1]=0  (T=1024)
//
// R14 = R13 with the legal PTX form of the L2 eviction hint:
//   createpolicy.fractional.L2::evict_last -> policy reg (hoisted),
//   ld.global.nc.L2::cache_hint.v4.f32 for phase-1 loads.
// Structure = R5 (sync-free, one 1024-thread CTA per tile, 2 CTAs/SM,
// 64 warps/SM, 78.6% DRAM busy) + eviction-priority control:
//   phase-1 loads pinned evict-last; stores __stcs (evict-first);
//   phase-3 re-reads __ldcs (demote at last use).
// 76MB pinned lines < 126MB L2 -> re-read hits; traffic ~1.03GB.

#define T_DIM 1024
#define S_DIM 64
#define THREADS 1024
#define T4 (T_DIM / 4)            // 256 float4 per row
#define S_PER_PART 16             // 64 synapse rows / 4 parts
#define TILE_F4 (S_DIM * T4)      // 16384 float4 per tile

__device__ __forceinline__ float4 ldg_hint(const float4* p, uint64_t pol) {
    float4 v;
    asm("ld.global.nc.L2::cache_hint.v4.f32 {%0,%1,%2,%3}, [%4], %5;"
        : "=f"(v.x), "=f"(v.y), "=f"(v.z), "=f"(v.w) : "l"(p), "l"(pol));
    return v;
}

__global__ __launch_bounds__(THREADS, 2)
void sdb_kernel(const float4* __restrict__ sp,
                const float* __restrict__ beta_p,
                float4* __restrict__ out) {
    __shared__ float4 red[THREADS];       // 16 KB synapse partials
    __shared__ float4 statS[T4];          // 4 KB broadcast stat
    __shared__ float Ms[8], As[8];

    const int tid  = threadIdx.x;
    const int col  = tid & (T4 - 1);      // 0..255 time chunk
    const int part = tid >> 8;            // 0..3 synapse partition
    const int lane = tid & 31;
    const int wid  = tid >> 5;            // 0..31 (part0 -> 0..7)
    const int s0r  = part * S_PER_PART;

    const size_t base = (size_t)blockIdx.x * TILE_F4;
    const float4* spb = sp + base;
    float4* ob = out + base;

    const float beta = beta_p[0];
    const float omb  = 1.0f - beta;

    // L2 policy: evict-last for the whole access stream of phase 1
    uint64_t pol;
    asm("createpolicy.fractional.L2::evict_last.b64 %0, 1.0;" : "=l"(pol));

    // ---------- Phase 1: partial sums, lines pinned evict-last in L2 ----------
    const float4* p = spb + (size_t)s0r * T4 + col;
    float4 acc0 = make_float4(0.f, 0.f, 0.f, 0.f);
    float4 acc1 = make_float4(0.f, 0.f, 0.f, 0.f);
    #pragma unroll
    for (int k = 0; k < S_PER_PART; k += 2) {
        float4 v0 = ldg_hint(&p[(size_t)k * T4], pol);
        float4 v1 = ldg_hint(&p[(size_t)(k + 1) * T4], pol);
        acc0.x += v0.x; acc0.y += v0.y; acc0.z += v0.z; acc0.w += v0.w;
        acc1.x += v1.x; acc1.y += v1.y; acc1.z += v1.z; acc1.w += v1.w;
    }
    acc0.x += acc1.x; acc0.y += acc1.y; acc0.z += acc1.z; acc0.w += acc1.w;
    red[tid] = acc0;
    __syncthreads();                      // barrier A

    // ---------- Phase 2: finish mean + parallel scan (warps 0..7) ----------
    if (part == 0) {
        float4 a4 = red[col];
        float4 b4 = red[col + 256];
        float4 c4 = red[col + 512];
        float4 d4 = red[col + 768];
        const float inv = 1.0f / (float)S_DIM;
        const float x0 = (a4.x + b4.x + c4.x + d4.x) * inv;
        const float x1 = (a4.y + b4.y + c4.y + d4.y) * inv;
        const float x2 = (a4.z + b4.z + c4.z + d4.z) * inv;
        const float x3 = (a4.w + b4.w + c4.w + d4.w) * inv;

        // per-thread composite over 4 time steps: state' = m*state + a
        float a = omb * x0;
        a = beta * a + omb * x1;
        a = beta * a + omb * x2;
        a = beta * a + omb * x3;
        float m = beta * beta;
        m = m * m;                        // beta^4

        // warp inclusive scan of (m, a)
        #pragma unroll
        for (int d = 1; d < 32; d <<= 1) {
            float ap = __shfl_up_sync(0xffffffffu, a, d);
            float mp = __shfl_up_sync(0xffffffffu, m, d);
            if (lane >= d) { a += m * ap; m *= mp; }
        }
        if (lane == 31) { Ms[wid] = m; As[wid] = a; }
        // sync only the 8 part-0 warps (256 threads): named barrier 1
        asm volatile("bar.sync 1, 256;" ::: "memory");

        // serial compose of warp aggregates [0..wid-1] (tiny)
        float pref = 0.0f;
        #pragma unroll
        for (int w = 0; w < 8; ++w) {
            if (w == wid) break;
            pref = Ms[w] * pref + As[w];
        }
        const float a_full = a + m * pref;
        const float a_prev = __shfl_up_sync(0xffffffffu, a_full, 1);
        const float a_excl = (lane > 0) ? a_prev : pref;

        float st = a_excl;
        st = beta * st + omb * x0; const float r0 = st;
        st = beta * st + omb * x1; const float r1 = st;
        st = beta * st + omb * x2; const float r2 = st;
        st = beta * st + omb * x3; const float r3 = st;
        statS[col] = make_float4(r0, r1, r2, r3);
    }
    __syncthreads();                      // barrier B

    // ---------- Phase 3: re-read (L2 hit, demote) and stream out ----------
    const float4 st4 = statS[col];
    float4* pw = ob + (size_t)s0r * T4 + col;
    #pragma unroll
    for (int k = 0; k < S_PER_PART; ++k) {
        float4 v = __ldcs(&p[(size_t)k * T4]);    // hit + evict-first demote
        float4 o;
        o.x = (1.0f - v.x) * st4.x;
        o.y = (1.0f - v.y) * st4.y;
        o.z = (1.0f - v.z) * st4.z;
        o.w = (1.0f - v.w) * st4.w;
        __stcs(&pw[(size_t)k * T4], o);           // streaming store
    }
}

extern "C" void kernel_launch(void* const* d_in, const int* in_sizes, int n_in,
                              void* d_out, int out_size) {
    const float* spikes = (const float*)d_in[0];
    const float* beta   = (const float*)d_in[1];
    float* out          = (float*)d_out;

    const int nbc = in_sizes[0] / (S_DIM * T_DIM);  // 16*128 = 2048 tiles

    sdb_kernel<<<nbc, THREADS>>>(
        (const float4*)spikes, beta, (float4*)out);
}

// round 16
// speedup vs baseline: 1.1775x; 1.1775x over previous
#include <cuda_runtime.h>
#include <cstdint>

// SignalDualBackground: out[b,c,s,t] = (1 - spikes[b,c,s,t]) * stat[b,c,t]
//   x[b,c,t]  = mean_s spikes[b,c,s,t]            (S=64)
//   stat[.,t] = beta*stat[.,t-1] + (1-beta)*x[.,t], stat[.,-1]=0  (T=1024)
//
// R15 = R7's per-tile pipeline (cluster-2 shared tile, symmetric DSMEM
// exchange + redundant per-rank scan, ONE cluster barrier per tile,
// ideal 1.02GB traffic) made PERSISTENT with atomic work stealing:
//  - grid = 2*SMs (one cluster per SM pair), each cluster loops over tiles
//  - first tile = cluster_id; subsequent tiles grabbed one-ahead by rank0
//    (atomicAdd) and DSMEM-pushed alongside the partials -> the existing
//    cluster barrier covers the handoff, NO extra syncs
//  - peerS/nextT parity double-buffered (one-ahead race)
//  - counter reset by last-finishing cluster -> graph-replay safe
// Removes ~14 wave transitions + tail imbalance (~10-15us).

#define T_DIM 1024
#define S_DIM 64
#define THREADS 1024
#define T4 (T_DIM / 4)              // 256 float4 per row
#define ROWS_PER_CTA 32
#define ROWS_PER_THREAD 8           // 32 rows / 4 parts
#define TILE_F4 (S_DIM * T4)        // 16384 float4 per tile

__device__ unsigned g_next = 0;     // dynamic-grab counter (reset each run)
__device__ unsigned g_done = 0;     // finished-cluster count (reset each run)

__device__ __forceinline__ uint32_t smem_u32(const void* p) {
    uint32_t a;
    asm("{ .reg .u64 t; cvta.to.shared.u64 t, %1; cvt.u32.u64 %0, t; }"
        : "=r"(a) : "l"(p));
    return a;
}

__global__ __launch_bounds__(THREADS, 2) __cluster_dims__(2, 1, 1)
void sdb_kernel(const float4* __restrict__ sp,
                const float* __restrict__ beta_p,
                float4* __restrict__ out,
                int n_tiles, int n_clusters) {
    __shared__ float4 red[THREADS];     // 16KB: per-thread partials
    __shared__ float4 statS[T4];        // 4KB: broadcast stat
    __shared__ float4 peerS[2][T4];     // 8KB: peer partials, double-buffered
    __shared__ float Ms[8], As[8];
    __shared__ unsigned nextT[2];       // next tile index, double-buffered

    const int tid  = threadIdx.x;
    const int col  = tid & (T4 - 1);    // 0..255 time chunk
    const int part = tid >> 8;          // 0..3
    const int lane = tid & 31;
    const int wid  = tid >> 5;          // part0 -> 0..7

    const int rank = (int)(blockIdx.x & 1);
    const int peer = rank ^ 1;
    const int cid  = (int)(blockIdx.x >> 1);

    const float beta = beta_p[0];
    const float omb  = 1.0f - beta;
    const float inv  = 1.0f / (float)S_DIM;

    int tile = cid;                     // first tile: static
    int parity = 0;

    while (tile < n_tiles) {
        const size_t base = (size_t)tile * TILE_F4;
        const int srow0 = rank * ROWS_PER_CTA + part * ROWS_PER_THREAD;
        const float4* p = sp + base + (size_t)srow0 * T4 + col;

        // ---------- Phase 1: partial sums over 8 rows/thread ----------
        float4 acc0 = make_float4(0.f, 0.f, 0.f, 0.f);
        float4 acc1 = make_float4(0.f, 0.f, 0.f, 0.f);
        #pragma unroll
        for (int k = 0; k < ROWS_PER_THREAD; k += 2) {
            float4 v0 = p[(size_t)k * T4];
            float4 v1 = p[(size_t)(k + 1) * T4];
            acc0.x += v0.x; acc0.y += v0.y; acc0.z += v0.z; acc0.w += v0.w;
            acc1.x += v1.x; acc1.y += v1.y; acc1.z += v1.z; acc1.w += v1.w;
        }
        acc0.x += acc1.x; acc0.y += acc1.y; acc0.z += acc1.z; acc0.w += acc1.w;
        red[tid] = acc0;
        __syncthreads();                // barrier A

        // part 0: CTA column sums + symmetric DSMEM push (double-buffered)
        float4 csum;
        if (part == 0) {
            float4 a4 = red[col];
            float4 b4 = red[col + 256];
            float4 c4 = red[col + 512];
            float4 d4 = red[col + 768];
            csum.x = a4.x + b4.x + c4.x + d4.x;
            csum.y = a4.y + b4.y + c4.y + d4.y;
            csum.z = a4.z + b4.z + c4.z + d4.z;
            csum.w = a4.w + b4.w + c4.w + d4.w;

            uint32_t la = smem_u32(&peerS[parity][col]);
            uint32_t ra;
            asm("mapa.shared::cluster.u32 %0, %1, %2;" : "=r"(ra) : "r"(la), "r"(peer));
            asm volatile("st.shared::cluster.v4.b32 [%0], {%1,%2,%3,%4};"
                :: "r"(ra),
                   "r"(__float_as_uint(csum.x)), "r"(__float_as_uint(csum.y)),
                   "r"(__float_as_uint(csum.z)), "r"(__float_as_uint(csum.w))
                : "memory");
        }
        // rank0 tid0 grabs the NEXT tile one-ahead; pushes to both CTAs
        if (rank == 0 && tid == 0) {
            unsigned nt = (unsigned)n_clusters + atomicAdd(&g_next, 1u);
            nextT[parity] = nt;
            uint32_t la = smem_u32(&nextT[parity]);
            uint32_t ra;
            asm("mapa.shared::cluster.u32 %0, %1, %2;" : "=r"(ra) : "r"(la), "r"(1));
            asm volatile("st.shared::cluster.u32 [%0], %1;"
                :: "r"(ra), "r"(nt) : "memory");
        }

        // single cluster barrier: partials + next-tile index visible
        asm volatile("barrier.cluster.arrive.aligned;" ::: "memory");
        asm volatile("barrier.cluster.wait.aligned;" ::: "memory");

        // ---------- Phase 2: BOTH ranks compute the scan (part 0) ----------
        if (part == 0) {
            float4 o4 = peerS[parity][col];
            const float x0 = (csum.x + o4.x) * inv;
            const float x1 = (csum.y + o4.y) * inv;
            const float x2 = (csum.z + o4.z) * inv;
            const float x3 = (csum.w + o4.w) * inv;

            // per-thread composite over 4 time steps: state' = m*state + a
            float a = omb * x0;
            a = beta * a + omb * x1;
            a = beta * a + omb * x2;
            a = beta * a + omb * x3;
            float m = beta * beta;
            m = m * m;                  // beta^4

            #pragma unroll
            for (int d = 1; d < 32; d <<= 1) {
                float ap = __shfl_up_sync(0xffffffffu, a, d);
                float mp = __shfl_up_sync(0xffffffffu, m, d);
                if (lane >= d) { a += m * ap; m *= mp; }
            }
            if (lane == 31) { Ms[wid] = m; As[wid] = a; }
            asm volatile("bar.sync 1, 256;" ::: "memory");  // 8 scan warps

            float pref = 0.0f;
            #pragma unroll
            for (int w = 0; w < 8; ++w) {
                if (w == wid) break;
                pref = Ms[w] * pref + As[w];
            }
            const float a_full = a + m * pref;
            const float a_prev = __shfl_up_sync(0xffffffffu, a_full, 1);
            const float a_excl = (lane > 0) ? a_prev : pref;

            float st = a_excl;
            st = beta * st + omb * x0; const float r0 = st;
            st = beta * st + omb * x1; const float r1 = st;
            st = beta * st + omb * x2; const float r2 = st;
            st = beta * st + omb * x3; const float r3 = st;
            statS[col] = make_float4(r0, r1, r2, r3);
        }
        __syncthreads();                // barrier B

        const int ntile = (int)nextT[parity];   // read after barrier B

        // ---------- Phase 3: out = (1-spike)*stat ; re-read hits L2 ----------
        const float4 st4 = statS[col];
        float4* pw = out + base + (size_t)srow0 * T4 + col;
        #pragma unroll
        for (int k = 0; k < ROWS_PER_THREAD; ++k) {
            float4 v = __ldcs(&p[(size_t)k * T4]);   // last use: evict-first
            float4 o;
            o.x = (1.0f - v.x) * st4.x;
            o.y = (1.0f - v.y) * st4.y;
            o.z = (1.0f - v.z) * st4.z;
            o.w = (1.0f - v.w) * st4.w;
            __stcs(&pw[(size_t)k * T4], o);          // streaming store
        }

        tile = ntile;
        parity ^= 1;
    }

    // last-finishing cluster resets the counters (graph-replay safe)
    if (rank == 0 && tid == 0) {
        unsigned d = atomicAdd(&g_done, 1u);
        if (d == (unsigned)n_clusters - 1u) {
            atomicExch(&g_next, 0u);
            atomicExch(&g_done, 0u);
        }
    }
}

extern "C" void kernel_launch(void* const* d_in, const int* in_sizes, int n_in,
                              void* d_out, int out_size) {
    const float* spikes = (const float*)d_in[0];
    const float* beta   = (const float*)d_in[1];
    float* out          = (float*)d_out;

    const int nbc = in_sizes[0] / (S_DIM * T_DIM);  // 2048 tiles

    int dev = 0, nsm = 148;
    cudaGetDevice(&dev);
    cudaDeviceGetAttribute(&nsm, cudaDevAttrMultiProcessorCount, dev);
    int n_clusters = nsm;                  // 2 CTAs per cluster, 2 CTAs/SM
    if (n_clusters > nbc) n_clusters = nbc;

    sdb_kernel<<<n_clusters * 2, THREADS>>>(
        (const float4*)spikes, beta, (float4*)out, nbc, n_clusters);
}

// round 17
// speedup vs baseline: 1.1872x; 1.0082x over previous
#include <cuda_runtime.h>
#include <cstdint>

// SignalDualBackground: out[b,c,s,t] = (1 - spikes[b,c,s,t]) * stat[b,c,t]
//   x[b,c,t]  = mean_s spikes[b,c,s,t]            (S=64)
//   stat[.,t] = beta*stat[.,t-1] + (1-beta)*x[.,t], stat[.,-1]=0  (T=1024)
//
// R16 = R7 (cluster-2 shared tile, symmetric DSMEM exchange + redundant
// per-rank scan, ideal 1.02GB traffic) with the mid-tile cluster barrier
// (~490cyc, couples both CTAs' 2048 threads) replaced by a lightweight
// DSMEM mbarrier handshake:
//   - mbarrier init (1 arrival) at top; init published via split cluster
//     barrier: arrive at kernel top, wait after barrier A (fast-path, the
//     peer arrived ~10k cycles earlier)
//   - part0 stores partials into peer's peerS, bar.sync 1,256 orders them,
//     elected thread release-arrives on the PEER's mbarrier
//   - part0 acquire-waits on its OWN mbarrier (try_wait ~90-150cyc)
//   - parts 1-3 never execute any cluster-scope sync
// Plus: phase 3 walks rows in REVERSE (most-recently-loaded first) for
// better L1/L2-LRU hits. No other changes vs R7.

#define T_DIM 1024
#define S_DIM 64
#define THREADS 1024
#define T4 (T_DIM / 4)              // 256 float4 per row
#define ROWS_PER_CTA 32
#define ROWS_PER_THREAD 8           // 32 rows / 4 parts
#define TILE_F4 (S_DIM * T4)        // 16384 float4 per tile

__device__ __forceinline__ uint32_t smem_u32(const void* p) {
    uint32_t a;
    asm("{ .reg .u64 t; cvta.to.shared.u64 t, %1; cvt.u32.u64 %0, t; }"
        : "=r"(a) : "l"(p));
    return a;
}

__global__ __launch_bounds__(THREADS, 2) __cluster_dims__(2, 1, 1)
void sdb_kernel(const float4* __restrict__ sp,
                const float* __restrict__ beta_p,
                float4* __restrict__ out) {
    __shared__ float4 red[THREADS];   // 16KB: per-thread partials
    __shared__ float4 statS[T4];      // 4KB: broadcast stat
    __shared__ float4 peerS[T4];      // 4KB: peer's 32-row column sums
    __shared__ float Ms[8], As[8];
    __shared__ uint64_t mbar;         // handshake barrier (1 arrival)

    const int tid  = threadIdx.x;
    const int col  = tid & (T4 - 1);  // 0..255 time chunk
    const int part = tid >> 8;        // 0..3
    const int lane = tid & 31;
    const int wid  = tid >> 5;        // part0 -> 0..7

    const int rank = (int)(blockIdx.x & 1);      // ctarank within cluster
    const int peer = rank ^ 1;
    const size_t base = (size_t)(blockIdx.x >> 1) * TILE_F4;
    const int srow0 = rank * ROWS_PER_CTA + part * ROWS_PER_THREAD;

    const float beta = beta_p[0];
    const float omb  = 1.0f - beta;

    // init handshake mbarrier; publish via split cluster barrier (arrive
    // here, wait after barrier A -> peer has long arrived by then)
    if (tid == 0) {
        uint32_t a = smem_u32(&mbar);
        asm volatile("mbarrier.init.shared.b64 [%0], %1;"
                     :: "r"(a), "r"(1u) : "memory");
    }
    asm volatile("barrier.cluster.arrive.aligned;" ::: "memory");

    // ---------- Phase 1: partial sums over this CTA's 8 rows/thread ----------
    const float4* p = sp + base + (size_t)srow0 * T4 + col;
    float4 acc0 = make_float4(0.f, 0.f, 0.f, 0.f);
    float4 acc1 = make_float4(0.f, 0.f, 0.f, 0.f);
    #pragma unroll
    for (int k = 0; k < ROWS_PER_THREAD; k += 2) {
        float4 v0 = p[(size_t)k * T4];
        float4 v1 = p[(size_t)(k + 1) * T4];
        acc0.x += v0.x; acc0.y += v0.y; acc0.z += v0.z; acc0.w += v0.w;
        acc1.x += v1.x; acc1.y += v1.y; acc1.z += v1.z; acc1.w += v1.w;
    }
    acc0.x += acc1.x; acc0.y += acc1.y; acc0.z += acc1.z; acc0.w += acc1.w;
    red[tid] = acc0;
    __syncthreads();                  // barrier A

    // peer's mbarrier init is now guaranteed visible (fast-path wait)
    asm volatile("barrier.cluster.wait.aligned;" ::: "memory");

    // ---------- Phase 2: exchange via DSMEM + mbarrier, scan (part 0) ----------
    if (part == 0) {
        float4 a4 = red[col];
        float4 b4 = red[col + 256];
        float4 c4 = red[col + 512];
        float4 d4 = red[col + 768];
        float4 csum;
        csum.x = a4.x + b4.x + c4.x + d4.x;
        csum.y = a4.y + b4.y + c4.y + d4.y;
        csum.z = a4.z + b4.z + c4.z + d4.z;
        csum.w = a4.w + b4.w + c4.w + d4.w;

        // push my CTA sums into the peer's peerS[col]
        {
            uint32_t la = smem_u32(&peerS[col]);
            uint32_t ra;
            asm("mapa.shared::cluster.u32 %0, %1, %2;" : "=r"(ra) : "r"(la), "r"(peer));
            asm volatile("st.shared::cluster.v4.b32 [%0], {%1,%2,%3,%4};"
                :: "r"(ra),
                   "r"(__float_as_uint(csum.x)), "r"(__float_as_uint(csum.y)),
                   "r"(__float_as_uint(csum.z)), "r"(__float_as_uint(csum.w))
                : "memory");
        }
        // order the 256 stores, then elected thread release-arrives on the
        // PEER's mbarrier (cumulative release covers all 256 stores)
        asm volatile("bar.sync 1, 256;" ::: "memory");
        if (tid == 0) {
            uint32_t la = smem_u32(&mbar);
            uint32_t ra;
            asm("mapa.shared::cluster.u32 %0, %1, %2;" : "=r"(ra) : "r"(la), "r"(peer));
            asm volatile("mbarrier.arrive.release.cluster.shared::cluster.b64 _, [%0];"
                         :: "r"(ra) : "memory");
        }
        // wait on OUR mbarrier for the peer's partials (acquire, parity 0)
        {
            uint32_t mb = smem_u32(&mbar);
            asm volatile(
                "{\n\t"
                ".reg .pred P1;\n\t"
                "WAIT_LOOP_%=:\n\t"
                "mbarrier.try_wait.parity.acquire.cluster.shared::cta.b64 P1, [%0], 0, 0x989680;\n\t"
                "@P1 bra.uni WAIT_DONE_%=;\n\t"
                "bra.uni WAIT_LOOP_%=;\n\t"
                "WAIT_DONE_%=:\n\t"
                "}"
                :: "r"(mb) : "memory");
        }

        float4 o4 = peerS[col];
        const float inv = 1.0f / (float)S_DIM;
        const float x0 = (csum.x + o4.x) * inv;
        const float x1 = (csum.y + o4.y) * inv;
        const float x2 = (csum.z + o4.z) * inv;
        const float x3 = (csum.w + o4.w) * inv;

        // per-thread composite over 4 time steps: state' = m*state + a
        float a = omb * x0;
        a = beta * a + omb * x1;
        a = beta * a + omb * x2;
        a = beta * a + omb * x3;
        float m = beta * beta;
        m = m * m;                    // beta^4

        #pragma unroll
        for (int d = 1; d < 32; d <<= 1) {
            float ap = __shfl_up_sync(0xffffffffu, a, d);
            float mp = __shfl_up_sync(0xffffffffu, m, d);
            if (lane >= d) { a += m * ap; m *= mp; }
        }
        if (lane == 31) { Ms[wid] = m; As[wid] = a; }
        asm volatile("bar.sync 1, 256;" ::: "memory");  // 8 scan warps only

        float pref = 0.0f;
        #pragma unroll
        for (int w = 0; w < 8; ++w) {
            if (w == wid) break;
            pref = Ms[w] * pref + As[w];
        }
        const float a_full = a + m * pref;
        const float a_prev = __shfl_up_sync(0xffffffffu, a_full, 1);
        const float a_excl = (lane > 0) ? a_prev : pref;

        float st = a_excl;
        st = beta * st + omb * x0; const float r0 = st;
        st = beta * st + omb * x1; const float r1 = st;
        st = beta * st + omb * x2; const float r2 = st;
        st = beta * st + omb * x3; const float r3 = st;
        statS[col] = make_float4(r0, r1, r2, r3);
    }
    __syncthreads();                  // barrier B: stat visible to all warps

    // ---------- Phase 3: out = (1-spike)*stat, REVERSE row order ----------
    const float4 st4 = statS[col];
    float4* pw = out + base + (size_t)srow0 * T4 + col;
    #pragma unroll
    for (int k = ROWS_PER_THREAD - 1; k >= 0; --k) {
        float4 v = __ldcs(&p[(size_t)k * T4]);   // last use: evict-first
        float4 o;
        o.x = (1.0f - v.x) * st4.x;
        o.y = (1.0f - v.y) * st4.y;
        o.z = (1.0f - v.z) * st4.z;
        o.w = (1.0f - v.w) * st4.w;
        __stcs(&pw[(size_t)k * T4], o);           // streaming store
    }
}

extern "C" void kernel_launch(void* const* d_in, const int* in_sizes, int n_in,
                              void* d_out, int out_size) {
    const float* spikes = (const float*)d_in[0];
    const float* beta   = (const float*)d_in[1];
    float* out          = (float*)d_out;

    const int nbc = in_sizes[0] / (S_DIM * T_DIM);  // 2048 tiles

    // one cluster (2 CTAs) per tile
    sdb_kernel<<<nbc * 2, THREADS>>>(
        (const float4*)spikes, beta, (float4*)out);
}